// round 8
// baseline (speedup 1.0000x reference)
#include <cuda_runtime.h>
#include <cuda_bf16.h>
#include <math.h>

// Problem constants
#define NN 4096
#define HH 512
#define TT 12

// ---------------- scratch (device globals; no allocs allowed) ----------------
__device__ float g_h0buf[NN * HH];     // h ping
__device__ float g_h1buf[NN * HH];     // h pong
__device__ float g_gzbuf[NN * 3 * HH]; // zx @ W_ih[:, :256]^T + b_ih (time-invariant)
__device__ float g_xbuf[NN * 2];       // current action input x_t

__device__ __forceinline__ float fast_sigmoid(float v) {
    return 1.f / (1.f + __expf(-v));
}
__device__ __forceinline__ float fast_tanh(float v) {
    // tanh(x) = 1 - 2/(exp(2x)+1); accuracy ~__expf ulp, fine vs 1e-3 budget
    return 1.f - 2.f / (__expf(2.f * v) + 1.f);
}

// ---------------- merged prologue GEMM ----------------
// Computes BOTH h0 = zx @ W_h0^T + b_h0 (blockIdx.y < 8) and
//          gz = zx @ W_ih[:, :256]^T + b_ih (blockIdx.y >= 8) in one launch.
// zx[n][k] = (k<128) ? z[n][k] : x[n][k-128]; K = 256.
// Tiles: BM=128 rows, BN=64 cols, KT=16. 256 threads, micro 8x4.
// Both ldw values (256, 258) are even -> row starts 8B-aligned -> float2 B loads.
__global__ __launch_bounds__(256, 2)
void prologue_gemm(const float* __restrict__ z, const float* __restrict__ x,
                   const float* __restrict__ W_h0, const float* __restrict__ b_h0,
                   const float* __restrict__ W_ih, const float* __restrict__ b_ih,
                   float* __restrict__ h0out, float* __restrict__ gzout) {
    __shared__ float As[16][132];
    __shared__ float Bs[16][68];

    // Select which GEMM this block belongs to (uniform per block).
    const bool is_h0 = (blockIdx.y < 8);
    const float* W   = is_h0 ? W_h0 : W_ih;
    const float* b   = is_h0 ? b_h0 : b_ih;
    float* out       = is_h0 ? h0out : gzout;
    const int ldw    = is_h0 ? 256 : 258;
    const int ncols  = is_h0 ? HH : 3 * HH;
    const int c0     = (is_h0 ? blockIdx.y : (blockIdx.y - 8)) * 64;

    const int r0 = blockIdx.x * 128;
    const int tid = threadIdx.x;
    const int ct = tid & 15;
    const int rt = tid >> 4;

    float acc[8][4];
#pragma unroll
    for (int i = 0; i < 8; i++)
#pragma unroll
        for (int j = 0; j < 4; j++) acc[i][j] = 0.f;

    for (int kb = 0; kb < 256; kb += 16) {
        const float* src = (kb < 128) ? z : x;
        const int ks = kb & 127;
        // A tile: 128 rows x 16 k = 512 float4 tasks
#pragma unroll
        for (int t2 = 0; t2 < 2; t2++) {
            int task = tid + 256 * t2;
            int r = task >> 2;
            int k4 = (task & 3) << 2;
            float4 v = *(const float4*)&src[(size_t)(r0 + r) * 128 + ks + k4];
            As[k4 + 0][r] = v.x; As[k4 + 1][r] = v.y;
            As[k4 + 2][r] = v.z; As[k4 + 3][r] = v.w;
        }
        // B tile: 64 cols x 16 k = 512 float2 tasks (8B-aligned since ldw even)
#pragma unroll
        for (int t2 = 0; t2 < 2; t2++) {
            int e = tid + 256 * t2;
            int c = e >> 3;               // 0..63
            int k2 = (e & 7) << 1;        // 0,2,..,14
            float2 v = *(const float2*)&W[(size_t)(c0 + c) * ldw + kb + k2];
            Bs[k2 + 0][c] = v.x;
            Bs[k2 + 1][c] = v.y;
        }
        __syncthreads();
#pragma unroll
        for (int k = 0; k < 16; k++) {
            float4 a0 = *(const float4*)&As[k][rt * 8];
            float4 a1 = *(const float4*)&As[k][rt * 8 + 4];
            float a[8] = {a0.x, a0.y, a0.z, a0.w, a1.x, a1.y, a1.z, a1.w};
            float bv[4];
#pragma unroll
            for (int i = 0; i < 4; i++) bv[i] = Bs[k][ct + 16 * i];
#pragma unroll
            for (int rr = 0; rr < 8; rr++)
#pragma unroll
                for (int i = 0; i < 4; i++)
                    acc[rr][i] = fmaf(a[rr], bv[i], acc[rr][i]);
        }
        __syncthreads();
    }

#pragma unroll
    for (int i = 0; i < 4; i++) {
        int c = c0 + ct + 16 * i;
        float bb = b[c];
#pragma unroll
        for (int rr = 0; rr < 8; rr++) {
            int n = r0 + rt * 8 + rr;
            out[(size_t)n * ncols + c] = acc[rr][i] + bb;
        }
    }
}

// ---------------- initial action a0 = x0 @ W_ia^T + b_ia ----------------
__global__ void a0_kernel(const float* __restrict__ x0,
                          const float* __restrict__ W_ia,
                          const float* __restrict__ b_ia,
                          float* __restrict__ xbuf) {
    int n = blockIdx.x * 256 + threadIdx.x;
    if (n >= NN) return;
    float4 v = *(const float4*)&x0[n * 4];
    float2 o;
    o.x = b_ia[0] + v.x * W_ia[0] + v.y * W_ia[1] + v.z * W_ia[2] + v.w * W_ia[3];
    o.y = b_ia[1] + v.x * W_ia[4] + v.y * W_ia[5] + v.z * W_ia[6] + v.w * W_ia[7];
    *(float2*)&xbuf[n * 2] = o;
}

// ---------------- fused GRU step: gh GEMM (h @ W_hh^T) + gate math ----------------
// Block tile: BM=128 rows, BJ=32 hidden units -> BN=96 gate-cols (3 gates).
// 256 threads, micro 8 rows x 6 cols (cols strided by 16; gates meet per thread).
// Double-buffered smem: 1 sync per k-tile, global loads for tile t+1 overlap
// compute on tile t.
__global__ __launch_bounds__(256, 2)
void gru_step_kernel(const float* __restrict__ h_in,
                     float* __restrict__ h_out,
                     const float* __restrict__ gz,
                     const float* __restrict__ x_t,
                     const float* __restrict__ W_hh,
                     const float* __restrict__ b_hh,
                     const float* __restrict__ W_ih) {
    __shared__ float As[2][16][132];  // h tile transposed: [buf][k][row]
    __shared__ float Bs[2][16][100];  // W tile transposed: [buf][k][gatecol]

    const int r0 = blockIdx.x * 128;
    const int j0 = blockIdx.y * 32;
    const int tid = threadIdx.x;
    const int ct = tid & 15;
    const int rt = tid >> 4;

    // Per-thread load coordinates (fixed across tiles)
    const int a_r0 = tid >> 2;
    const int a_k0 = (tid & 3) << 2;

    float acc[8][6];
#pragma unroll
    for (int i = 0; i < 8; i++)
#pragma unroll
        for (int j = 0; j < 6; j++) acc[i][j] = 0.f;

    // ---- tile loader: global -> smem buffer p for k-block kb ----
    auto load_tile = [&](int p, int kb) {
        // A tile: 128 rows x 16 k = 512 float4 tasks, 2 per thread
#pragma unroll
        for (int t2 = 0; t2 < 2; t2++) {
            int r = a_r0 + 64 * t2;
            float4 v = *(const float4*)&h_in[(size_t)(r0 + r) * HH + kb + a_k0];
            As[p][a_k0 + 0][r] = v.x; As[p][a_k0 + 1][r] = v.y;
            As[p][a_k0 + 2][r] = v.z; As[p][a_k0 + 3][r] = v.w;
        }
        // B tile: 96 gate-cols x 16 k = 384 float4 tasks
        for (int task = tid; task < 384; task += 256) {
            int cc = task >> 2;             // 0..95
            int k4 = (task & 3) << 2;
            int g = cc >> 5;                // gate
            int jj = cc & 31;
            float4 v = *(const float4*)&W_hh[(size_t)(g * HH + j0 + jj) * HH + kb + k4];
            Bs[p][k4 + 0][cc] = v.x; Bs[p][k4 + 1][cc] = v.y;
            Bs[p][k4 + 2][cc] = v.z; Bs[p][k4 + 3][cc] = v.w;
        }
    };

    load_tile(0, 0);
    __syncthreads();

    const int NKT = HH / 16;  // 32 k-tiles
    for (int t = 0; t < NKT; t++) {
        int p = t & 1;
        // Prefetch next tile into the other buffer (safe: the sync ending the
        // previous iteration guaranteed all compute on buffer 1-p finished).
        if (t + 1 < NKT) load_tile(1 - p, (t + 1) * 16);
        // Compute on buffer p
#pragma unroll
        for (int k = 0; k < 16; k++) {
            float4 a0 = *(const float4*)&As[p][k][rt * 8];
            float4 a1 = *(const float4*)&As[p][k][rt * 8 + 4];
            float a[8] = {a0.x, a0.y, a0.z, a0.w, a1.x, a1.y, a1.z, a1.w};
            float bv[6];
#pragma unroll
            for (int i = 0; i < 6; i++) bv[i] = Bs[p][k][ct + 16 * i];
#pragma unroll
            for (int rr = 0; rr < 8; rr++)
#pragma unroll
                for (int i = 0; i < 6; i++)
                    acc[rr][i] = fmaf(a[rr], bv[i], acc[rr][i]);
        }
        __syncthreads();
    }

    // Epilogue: thread owns hidden units j = j0+ct and j0+ct+16, rows rt*8..rt*8+7.
    // acc col index: i = 2*gate + s, where s selects j offset {+0, +16}.
    int jv[2] = {j0 + ct, j0 + ct + 16};
    float bh_r[2], bh_z[2], bh_n[2];
    float wr0[2], wr1[2], wz0[2], wz1[2], wn0[2], wn1[2];
#pragma unroll
    for (int s = 0; s < 2; s++) {
        int j = jv[s];
        bh_r[s] = __ldg(&b_hh[j]);
        bh_z[s] = __ldg(&b_hh[HH + j]);
        bh_n[s] = __ldg(&b_hh[2 * HH + j]);
        wr0[s] = __ldg(&W_ih[(size_t)j * 258 + 256]);            wr1[s] = __ldg(&W_ih[(size_t)j * 258 + 257]);
        wz0[s] = __ldg(&W_ih[(size_t)(HH + j) * 258 + 256]);     wz1[s] = __ldg(&W_ih[(size_t)(HH + j) * 258 + 257]);
        wn0[s] = __ldg(&W_ih[(size_t)(2 * HH + j) * 258 + 256]); wn1[s] = __ldg(&W_ih[(size_t)(2 * HH + j) * 258 + 257]);
    }

#pragma unroll
    for (int rr = 0; rr < 8; rr++) {
        int n = r0 + rt * 8 + rr;
        float2 xv = *(const float2*)&x_t[n * 2];   // one LDG.64 per row
        const float* gzr = gz + (size_t)n * (3 * HH);
#pragma unroll
        for (int s = 0; s < 2; s++) {
            int j = jv[s];
            float gir = __ldg(&gzr[j])          + xv.x * wr0[s] + xv.y * wr1[s];
            float giz = __ldg(&gzr[HH + j])     + xv.x * wz0[s] + xv.y * wz1[s];
            float gin = __ldg(&gzr[2 * HH + j]) + xv.x * wn0[s] + xv.y * wn1[s];
            float ghr = acc[rr][0 + s] + bh_r[s];
            float ghz = acc[rr][2 + s] + bh_z[s];
            float ghn = acc[rr][4 + s] + bh_n[s];
            float rg = fast_sigmoid(gir + ghr);
            float ug = fast_sigmoid(giz + ghz);
            float ng = fast_tanh(gin + rg * ghn);
            float hold = __ldg(&h_in[(size_t)n * HH + j]);
            h_out[(size_t)n * HH + j] = ng + ug * (hold - ng);
        }
    }
}

// ---------------- output projection: out = h_new @ W_out^T + b_out ----------------
// One warp per row; also feeds x_{t+1} back. 512 threads = 16 rows/block.
__global__ __launch_bounds__(512)
void out_proj_kernel(const float* __restrict__ h,
                     const float* __restrict__ W_out,
                     const float* __restrict__ b_out,
                     float* __restrict__ xbuf,
                     float* __restrict__ dout, int t) {
    int tid = threadIdx.x;
    int warp = tid >> 5, lane = tid & 31;
    int n = blockIdx.x * 16 + warp;
    const float* hr = h + (size_t)n * HH;
    float s0 = 0.f, s1 = 0.f;
#pragma unroll
    for (int k = lane * 4; k < HH; k += 128) {
        float4 hv = *(const float4*)&hr[k];
        float4 w0 = *(const float4*)&W_out[k];
        float4 w1 = *(const float4*)&W_out[HH + k];
        s0 += hv.x * w0.x + hv.y * w0.y + hv.z * w0.z + hv.w * w0.w;
        s1 += hv.x * w1.x + hv.y * w1.y + hv.z * w1.z + hv.w * w1.w;
    }
#pragma unroll
    for (int off = 16; off; off >>= 1) {
        s0 += __shfl_xor_sync(0xFFFFFFFFu, s0, off);
        s1 += __shfl_xor_sync(0xFFFFFFFFu, s1, off);
    }
    if (lane == 0) {
        float2 o;
        o.x = s0 + b_out[0];
        o.y = s1 + b_out[1];
        *(float2*)&xbuf[n * 2] = o;
        *(float2*)&dout[((size_t)n * TT + t) * 2] = o;
    }
}

// ---------------- launch ----------------
extern "C" void kernel_launch(void* const* d_in, const int* in_sizes, int n_in,
                              void* d_out, int out_size) {
    const float* z     = (const float*)d_in[0];
    const float* x     = (const float*)d_in[1];
    const float* x_0   = (const float*)d_in[2];
    const float* W_ia  = (const float*)d_in[3];
    const float* b_ia  = (const float*)d_in[4];
    const float* W_h0  = (const float*)d_in[5];
    const float* b_h0  = (const float*)d_in[6];
    const float* W_ih  = (const float*)d_in[7];
    const float* b_ih  = (const float*)d_in[8];
    const float* W_hh  = (const float*)d_in[9];
    const float* b_hh  = (const float*)d_in[10];
    const float* W_out = (const float*)d_in[11];
    const float* b_out = (const float*)d_in[12];
    float* out = (float*)d_out;

    float *hA, *hB, *gzb, *xb;
    cudaGetSymbolAddress((void**)&hA,  g_h0buf);
    cudaGetSymbolAddress((void**)&hB,  g_h1buf);
    cudaGetSymbolAddress((void**)&gzb, g_gzbuf);
    cudaGetSymbolAddress((void**)&xb,  g_xbuf);

    // Merged prologue: blockIdx.y<8 -> h0 (512 cols), else gz (1536 cols).
    prologue_gemm<<<dim3(NN / 128, 8 + 24), 256>>>(z, x, W_h0, b_h0, W_ih, b_ih, hA, gzb);
    // a0
    a0_kernel<<<NN / 256, 256>>>(x_0, W_ia, b_ia, xb);

    for (int t = 0; t < TT; t++) {
        gru_step_kernel<<<dim3(NN / 128, HH / 32), 256>>>(hA, hB, gzb, xb, W_hh, b_hh, W_ih);
        out_proj_kernel<<<NN / 16, 512>>>(hB, W_out, b_out, xb, out, t);
        float* tmp = hA; hA = hB; hB = tmp;
    }
}